// round 1
// baseline (speedup 1.0000x reference)
#include <cuda_runtime.h>
#include <cstdint>

// TinyRNN: B=4096, T=2048, I=1, H=12, O=2
// Layout: 4 lanes per batch element (lane k owns hidden rows 3k..3k+2),
// 8 batches per warp, 128-thread CTAs (32 batches), grid = 128 CTAs.

#define T_TOTAL 2048
#define NCHUNK  32
#define CH      64
#define XSTRIDE 68   // 64 + 4 pad: conflict-free smem reads, float4-aligned

__device__ __forceinline__ float tanh_fast(float a) {
    // tanh(a) = 1 - 2/(exp(2a)+1), via MUFU ex2 + rcp (~1e-6 rel err)
    float p = a * 2.885390081777927f;   // 2*log2(e)
    float e;
    asm("ex2.approx.f32 %0, %1;" : "=f"(e) : "f"(p));
    float d = e + 1.0f;
    float r;
    asm("rcp.approx.f32 %0, %1;" : "=f"(r) : "f"(d));
    return fmaf(-2.0f, r, 1.0f);
}

__global__ void __launch_bounds__(128, 1) tinyrnn_kernel(
    const float* __restrict__ x,       // [4096, 2048, 1]
    const float* __restrict__ W_ih,    // [12, 1]
    const float* __restrict__ W_hh,    // [12, 12]
    const float* __restrict__ b_ih,    // [12]
    const float* __restrict__ b_hh,    // [12]
    const float* __restrict__ W_head,  // [2, 12]
    const float* __restrict__ b_head,  // [2]
    float* __restrict__ out)           // [4096, 2]
{
    __shared__ float sx[2][32 * XSTRIDE];

    const int tid  = threadIdx.x;
    const int lane = tid & 31;
    const int warp = tid >> 5;
    const int k    = lane & 3;              // hidden-row slice (0..3)
    const int wb   = lane >> 2;             // batch within warp (0..7)
    const int bic  = warp * 8 + wb;         // batch in CTA (0..31)
    const int batch = blockIdx.x * 32 + bic;
    const int r0   = k * 3;

    // --- weights into registers ---
    float W0[12], W1[12], W2[12];
#pragma unroll
    for (int m = 0; m < 12; m++) {
        W0[m] = W_hh[(r0 + 0) * 12 + m];
        W1[m] = W_hh[(r0 + 1) * 12 + m];
        W2[m] = W_hh[(r0 + 2) * 12 + m];
    }
    const float wih0 = W_ih[r0 + 0];
    const float wih1 = W_ih[r0 + 1];
    const float wih2 = W_ih[r0 + 2];
    const float bb0 = b_ih[r0 + 0] + b_hh[r0 + 0];
    const float bb1 = b_ih[r0 + 1] + b_hh[r0 + 1];
    const float bb2 = b_ih[r0 + 2] + b_hh[r0 + 2];

    const float* xcta = x + (size_t)blockIdx.x * 32 * T_TOTAL;

    // --- cp.async chunk prefetch: 32 batches x 64 steps = 512 float4 ---
    auto prefetch = [&](int c, int buf) {
#pragma unroll
        for (int r = 0; r < 4; r++) {
            int flat = r * 128 + tid;       // 0..511
            int b    = flat >> 4;           // batch in CTA
            int q    = flat & 15;           // float4 within chunk
            const float* src = xcta + (size_t)b * T_TOTAL + c * CH + q * 4;
            unsigned dst = (unsigned)__cvta_generic_to_shared(
                &sx[buf][b * XSTRIDE + q * 4]);
            asm volatile("cp.async.ca.shared.global [%0], [%1], 16;\n"
                         :: "r"(dst), "l"(src));
        }
        asm volatile("cp.async.commit_group;\n");
    };

    prefetch(0, 0);

    float h0 = 0.0f, h1 = 0.0f, h2 = 0.0f;

    for (int c = 0; c < NCHUNK; c++) {
        const int cur = c & 1;
        if (c + 1 < NCHUNK) {
            prefetch(c + 1, cur ^ 1);
            asm volatile("cp.async.wait_group 1;\n");
        } else {
            asm volatile("cp.async.wait_group 0;\n");
        }
        __syncthreads();

        const float* xs = &sx[cur][bic * XSTRIDE];

#pragma unroll 4
        for (int tt = 0; tt < CH; tt++) {
            const float xt = xs[tt];

            // gather full h (12 values) from the 4-lane group
            float g[12];
#pragma unroll
            for (int m = 0; m < 4; m++) {
                g[3 * m + 0] = __shfl_sync(0xffffffffu, h0, m, 4);
                g[3 * m + 1] = __shfl_sync(0xffffffffu, h1, m, 4);
                g[3 * m + 2] = __shfl_sync(0xffffffffu, h2, m, 4);
            }

            float s0a = fmaf(xt, wih0, bb0), s0b = 0.0f;
            float s1a = fmaf(xt, wih1, bb1), s1b = 0.0f;
            float s2a = fmaf(xt, wih2, bb2), s2b = 0.0f;
#pragma unroll
            for (int m = 0; m < 6; m++) {
                s0a = fmaf(W0[m], g[m], s0a);
                s1a = fmaf(W1[m], g[m], s1a);
                s2a = fmaf(W2[m], g[m], s2a);
            }
#pragma unroll
            for (int m = 6; m < 12; m++) {
                s0b = fmaf(W0[m], g[m], s0b);
                s1b = fmaf(W1[m], g[m], s1b);
                s2b = fmaf(W2[m], g[m], s2b);
            }
            h0 = tanh_fast(s0a + s0b);
            h1 = tanh_fast(s1a + s1b);
            h2 = tanh_fast(s2a + s2b);
        }
        __syncthreads();
    }

    // --- head on final hidden state ---
    float g[12];
#pragma unroll
    for (int m = 0; m < 4; m++) {
        g[3 * m + 0] = __shfl_sync(0xffffffffu, h0, m, 4);
        g[3 * m + 1] = __shfl_sync(0xffffffffu, h1, m, 4);
        g[3 * m + 2] = __shfl_sync(0xffffffffu, h2, m, 4);
    }
    if (k == 0) {
        float o0 = b_head[0];
        float o1 = b_head[1];
#pragma unroll
        for (int m = 0; m < 12; m++) {
            o0 = fmaf(W_head[m],      g[m], o0);
            o1 = fmaf(W_head[12 + m], g[m], o1);
        }
        out[batch * 2 + 0] = o0;
        out[batch * 2 + 1] = o1;
    }
}

extern "C" void kernel_launch(void* const* d_in, const int* in_sizes, int n_in,
                              void* d_out, int out_size)
{
    const float* x      = (const float*)d_in[0];
    const float* W_ih   = (const float*)d_in[1];
    const float* W_hh   = (const float*)d_in[2];
    const float* b_ih   = (const float*)d_in[3];
    const float* b_hh   = (const float*)d_in[4];
    const float* W_head = (const float*)d_in[5];
    const float* b_head = (const float*)d_in[6];
    float* out = (float*)d_out;

    tinyrnn_kernel<<<128, 128>>>(x, W_ih, W_hh, b_ih, b_hh, W_head, b_head, out);
}

// round 2
// speedup vs baseline: 1.0145x; 1.0145x over previous
#include <cuda_runtime.h>
#include <cstdint>

// TinyRNN: B=4096, T=2048, I=1, H=12, O=2
// 4 lanes/batch; lane k owns rows {k, k+4, k+8}; 8 batches/warp;
// 128-thread CTAs (32 batches), grid = 128 CTAs -> 512 warps.
// State carried as r[m] = rcp(exp(2 s_m)+1)  (h = 1 - 2 r), weights pre-folded.

#define T_TOTAL 2048
#define NCHUNK  32
#define CH      64
#define XSTRIDE 68   // 64 + 4 pad

__device__ __forceinline__ uint64_t pack2(float lo, float hi) {
    uint64_t r; asm("mov.b64 %0, {%1, %2};" : "=l"(r) : "f"(lo), "f"(hi)); return r;
}
__device__ __forceinline__ void unpack2(uint64_t v, float &lo, float &hi) {
    asm("mov.b64 {%0, %1}, %2;" : "=f"(lo), "=f"(hi) : "l"(v));
}
__device__ __forceinline__ uint64_t mul2(uint64_t a, uint64_t b) {
    uint64_t r; asm("mul.rn.f32x2 %0, %1, %2;" : "=l"(r) : "l"(a), "l"(b)); return r;
}
__device__ __forceinline__ uint64_t fma2(uint64_t a, uint64_t b, uint64_t c) {
    uint64_t r; asm("fma.rn.f32x2 %0, %1, %2, %3;" : "=l"(r) : "l"(a), "l"(b), "l"(c)); return r;
}
__device__ __forceinline__ uint64_t add2(uint64_t a, uint64_t b) {
    uint64_t r; asm("add.rn.f32x2 %0, %1, %2;" : "=l"(r) : "l"(a), "l"(b)); return r;
}
__device__ __forceinline__ float ex2f(float x) {
    float r; asm("ex2.approx.f32 %0, %1;" : "=f"(r) : "f"(x)); return r;
}
__device__ __forceinline__ float rcpf(float x) {
    float r; asm("rcp.approx.f32 %0, %1;" : "=f"(r) : "f"(x)); return r;
}

__global__ void __launch_bounds__(128, 1) tinyrnn_kernel(
    const float* __restrict__ x,       // [4096, 2048, 1]
    const float* __restrict__ W_ih,    // [12, 1]
    const float* __restrict__ W_hh,    // [12, 12]
    const float* __restrict__ b_ih,    // [12]
    const float* __restrict__ b_hh,    // [12]
    const float* __restrict__ W_head,  // [2, 12]
    const float* __restrict__ b_head,  // [2]
    float* __restrict__ out)           // [4096, 2]
{
    __shared__ float sx[2][32 * XSTRIDE];

    const int tid  = threadIdx.x;
    const int lane = tid & 31;
    const int warp = tid >> 5;
    const int k    = lane & 3;              // lane within 4-lane group
    const int wb   = lane >> 2;             // batch within warp (0..7)
    const int bic  = warp * 8 + wb;         // batch in CTA (0..31)
    const int batch = blockIdx.x * 32 + bic;

    const float C2 = 2.885390081777927f;    // 2*log2(e)
    const float KN = -2.0f * C2;            // folded (1 - 2r) coefficient

    // --- fold weights per owned row: rows k, k+4, k+8 ---
    uint64_t Wp[3][6];      // packed m-pair weights, scaled by -2*C2
    float A[3], Bx[3];      // A = C2*(b_ih+b_hh+sum(W_row)); Bx = C2*W_ih[row]
#pragma unroll
    for (int i = 0; i < 3; i++) {
        const int row = k + 4 * i;
        float sumW = 0.0f;
        float wrow[12];
#pragma unroll
        for (int m = 0; m < 12; m++) {
            wrow[m] = W_hh[row * 12 + m];
            sumW += wrow[m];
        }
#pragma unroll
        for (int j = 0; j < 6; j++)
            Wp[i][j] = pack2(KN * wrow[2 * j], KN * wrow[2 * j + 1]);
        A[i]  = C2 * (b_ih[row] + b_hh[row] + sumW);
        Bx[i] = C2 * W_ih[row];
    }

    const float* xcta = x + (size_t)blockIdx.x * 32 * T_TOTAL;

    // --- cp.async chunk prefetch: 32 batches x 64 steps = 512 float4 ---
    auto prefetch = [&](int c, int buf) {
#pragma unroll
        for (int rr = 0; rr < 4; rr++) {
            int flat = rr * 128 + tid;      // 0..511
            int b    = flat >> 4;
            int q    = flat & 15;
            const float* src = xcta + (size_t)b * T_TOTAL + c * CH + q * 4;
            unsigned dst = (unsigned)__cvta_generic_to_shared(
                &sx[buf][b * XSTRIDE + q * 4]);
            asm volatile("cp.async.ca.shared.global [%0], [%1], 16;\n"
                         :: "r"(dst), "l"(src));
        }
        asm volatile("cp.async.commit_group;\n");
    };

    prefetch(0, 0);

    // state: r[m] = rcp(exp(2 s)+1); h=0 -> r=0.5
    float r0 = 0.5f, r1 = 0.5f, r2 = 0.5f;

    for (int c = 0; c < NCHUNK; c++) {
        const int cur = c & 1;
        if (c + 1 < NCHUNK) {
            prefetch(c + 1, cur ^ 1);
            asm volatile("cp.async.wait_group 1;\n");
        } else {
            asm volatile("cp.async.wait_group 0;\n");
        }
        __syncthreads();

        const float* xs = &sx[cur][bic * XSTRIDE];

#pragma unroll 4
        for (int tt = 0; tt < CH; tt++) {
            const float xt = xs[tt];

            // gather r's from 4-lane group, pack into 6 m-pairs
            uint64_t p0, p1, p2, p3, p4, p5;
            {
                float a, b, cc, d;
                a  = __shfl_sync(0xffffffffu, r0, 0, 4);
                b  = __shfl_sync(0xffffffffu, r0, 1, 4);
                cc = __shfl_sync(0xffffffffu, r0, 2, 4);
                d  = __shfl_sync(0xffffffffu, r0, 3, 4);
                p0 = pack2(a, b); p1 = pack2(cc, d);
                a  = __shfl_sync(0xffffffffu, r1, 0, 4);
                b  = __shfl_sync(0xffffffffu, r1, 1, 4);
                cc = __shfl_sync(0xffffffffu, r1, 2, 4);
                d  = __shfl_sync(0xffffffffu, r1, 3, 4);
                p2 = pack2(a, b); p3 = pack2(cc, d);
                a  = __shfl_sync(0xffffffffu, r2, 0, 4);
                b  = __shfl_sync(0xffffffffu, r2, 1, 4);
                cc = __shfl_sync(0xffffffffu, r2, 2, 4);
                d  = __shfl_sync(0xffffffffu, r2, 3, 4);
                p4 = pack2(a, b); p5 = pack2(cc, d);
            }

            float rn[3];
#pragma unroll
            for (int i = 0; i < 3; i++) {
                uint64_t aA = mul2(Wp[i][0], p0);
                uint64_t aB = mul2(Wp[i][1], p1);
                aA = fma2(Wp[i][2], p2, aA);
                aB = fma2(Wp[i][3], p3, aB);
                aA = fma2(Wp[i][4], p4, aA);
                aB = fma2(Wp[i][5], p5, aB);
                float lo, hi;
                unpack2(add2(aA, aB), lo, hi);
                float s = (lo + hi) + fmaf(xt, Bx[i], A[i]);
                rn[i] = rcpf(ex2f(s) + 1.0f);
            }
            r0 = rn[0]; r1 = rn[1]; r2 = rn[2];
        }
        __syncthreads();
    }

    // --- head on final hidden state: h[m] = 1 - 2 r[m] ---
    float g[12];
#pragma unroll
    for (int m = 0; m < 4; m++) {
        g[m + 0] = __shfl_sync(0xffffffffu, r0, m, 4);
        g[m + 4] = __shfl_sync(0xffffffffu, r1, m, 4);
        g[m + 8] = __shfl_sync(0xffffffffu, r2, m, 4);
    }
    if (k == 0) {
        float o0 = b_head[0];
        float o1 = b_head[1];
#pragma unroll
        for (int m = 0; m < 12; m++) {
            float h = fmaf(-2.0f, g[m], 1.0f);
            o0 = fmaf(W_head[m],      h, o0);
            o1 = fmaf(W_head[12 + m], h, o1);
        }
        out[batch * 2 + 0] = o0;
        out[batch * 2 + 1] = o1;
    }
}

extern "C" void kernel_launch(void* const* d_in, const int* in_sizes, int n_in,
                              void* d_out, int out_size)
{
    const float* x      = (const float*)d_in[0];
    const float* W_ih   = (const float*)d_in[1];
    const float* W_hh   = (const float*)d_in[2];
    const float* b_ih   = (const float*)d_in[3];
    const float* b_hh   = (const float*)d_in[4];
    const float* W_head = (const float*)d_in[5];
    const float* b_head = (const float*)d_in[6];
    float* out = (float*)d_out;

    tinyrnn_kernel<<<128, 128>>>(x, W_ih, W_hh, b_ih, b_hh, W_head, b_head, out);
}

// round 3
// speedup vs baseline: 1.0522x; 1.0371x over previous
#include <cuda_runtime.h>
#include <cstdint>

// TinyRNN: B=4096, T=2048, I=1, H=12, O=2
// 4 lanes/batch; lane k owns rows {k, k+4, k+8}; 8 batches/warp;
// 128-thread CTAs (32 batches), grid = 128 CTAs -> 512 warps.
// State carried as r[m] = rcp(exp(2 s_m)+1)  (h = 1 - 2 r), weights pre-folded.
// h-exchange via shared memory (STS x3 + syncwarp + LDS.128 x3), giving
// f32x2 operand pairs directly from aligned vector loads.

#define T_TOTAL 2048
#define NCHUNK  32
#define CH      64
#define XSTRIDE 68   // 64 + 4 pad
#define EXSTRIDE 20  // floats per batch exchange slot (80B: conflict-free)

__device__ __forceinline__ uint64_t pack2(float lo, float hi) {
    uint64_t r; asm("mov.b64 %0, {%1, %2};" : "=l"(r) : "f"(lo), "f"(hi)); return r;
}
__device__ __forceinline__ uint64_t pack2u(uint32_t lo, uint32_t hi) {
    uint64_t r; asm("mov.b64 %0, {%1, %2};" : "=l"(r) : "r"(lo), "r"(hi)); return r;
}
__device__ __forceinline__ void unpack2(uint64_t v, float &lo, float &hi) {
    asm("mov.b64 {%0, %1}, %2;" : "=f"(lo), "=f"(hi) : "l"(v));
}
__device__ __forceinline__ uint64_t mul2(uint64_t a, uint64_t b) {
    uint64_t r; asm("mul.rn.f32x2 %0, %1, %2;" : "=l"(r) : "l"(a), "l"(b)); return r;
}
__device__ __forceinline__ uint64_t fma2(uint64_t a, uint64_t b, uint64_t c) {
    uint64_t r; asm("fma.rn.f32x2 %0, %1, %2, %3;" : "=l"(r) : "l"(a), "l"(b), "l"(c)); return r;
}
__device__ __forceinline__ uint64_t add2(uint64_t a, uint64_t b) {
    uint64_t r; asm("add.rn.f32x2 %0, %1, %2;" : "=l"(r) : "l"(a), "l"(b)); return r;
}
__device__ __forceinline__ float ex2f(float x) {
    float r; asm("ex2.approx.f32 %0, %1;" : "=f"(r) : "f"(x)); return r;
}
__device__ __forceinline__ float rcpf(float x) {
    float r; asm("rcp.approx.f32 %0, %1;" : "=f"(r) : "f"(x)); return r;
}

__global__ void __launch_bounds__(128, 1) tinyrnn_kernel(
    const float* __restrict__ x,       // [4096, 2048, 1]
    const float* __restrict__ W_ih,    // [12, 1]
    const float* __restrict__ W_hh,    // [12, 12]
    const float* __restrict__ b_ih,    // [12]
    const float* __restrict__ b_hh,    // [12]
    const float* __restrict__ W_head,  // [2, 12]
    const float* __restrict__ b_head,  // [2]
    float* __restrict__ out)           // [4096, 2]
{
    __shared__ float sx[2][32 * XSTRIDE];
    __shared__ __align__(16) float sex[32 * EXSTRIDE];

    const int tid  = threadIdx.x;
    const int lane = tid & 31;
    const int warp = tid >> 5;
    const int k    = lane & 3;              // lane within 4-lane group
    const int wb   = lane >> 2;             // batch within warp (0..7)
    const int bic  = warp * 8 + wb;         // batch in CTA (0..31)
    const int batch = blockIdx.x * 32 + bic;

    const float C2 = 2.885390081777927f;    // 2*log2(e)
    const float KN = -2.0f * C2;            // folded (1 - 2r) coefficient

    // --- fold weights per owned row: rows k, k+4, k+8 ---
    uint64_t Wp[3][6];      // packed m-pair weights, scaled by -2*C2
    float A[3], Bx[3];      // A = C2*(b_ih+b_hh+sum(W_row)); Bx = C2*W_ih[row]
#pragma unroll
    for (int i = 0; i < 3; i++) {
        const int row = k + 4 * i;
        float sumW = 0.0f;
        float wrow[12];
#pragma unroll
        for (int m = 0; m < 12; m++) {
            wrow[m] = W_hh[row * 12 + m];
            sumW += wrow[m];
        }
#pragma unroll
        for (int j = 0; j < 6; j++)
            Wp[i][j] = pack2(KN * wrow[2 * j], KN * wrow[2 * j + 1]);
        A[i]  = C2 * (b_ih[row] + b_hh[row] + sumW);
        Bx[i] = C2 * W_ih[row];
    }

    // exchange-slot shared addresses
    const unsigned exb = (unsigned)__cvta_generic_to_shared(&sex[bic * EXSTRIDE]);
    const unsigned stA = exb + 4u * (unsigned)k;        // m = k
    const unsigned stB = stA + 16u;                     // m = k+4
    const unsigned stC = stA + 32u;                     // m = k+8

    const float* xcta = x + (size_t)blockIdx.x * 32 * T_TOTAL;

    // --- cp.async chunk prefetch: 32 batches x 64 steps = 512 float4 ---
    auto prefetch = [&](int c, int buf) {
#pragma unroll
        for (int rr = 0; rr < 4; rr++) {
            int flat = rr * 128 + tid;      // 0..511
            int b    = flat >> 4;
            int q    = flat & 15;
            const float* src = xcta + (size_t)b * T_TOTAL + c * CH + q * 4;
            unsigned dst = (unsigned)__cvta_generic_to_shared(
                &sx[buf][b * XSTRIDE + q * 4]);
            asm volatile("cp.async.ca.shared.global [%0], [%1], 16;\n"
                         :: "r"(dst), "l"(src));
        }
        asm volatile("cp.async.commit_group;\n");
    };

    prefetch(0, 0);

    // state: r[m] = rcp(exp(2 s)+1); h=0 -> r=0.5
    float r0 = 0.5f, r1 = 0.5f, r2 = 0.5f;

    for (int c = 0; c < NCHUNK; c++) {
        const int cur = c & 1;
        if (c + 1 < NCHUNK) {
            prefetch(c + 1, cur ^ 1);
            asm volatile("cp.async.wait_group 1;\n");
        } else {
            asm volatile("cp.async.wait_group 0;\n");
        }
        __syncthreads();

        const float* xs = &sx[cur][bic * XSTRIDE];

#pragma unroll 2
        for (int tt = 0; tt < CH; tt++) {
            const float xt = xs[tt];
            // bias/x terms, independent of state -> off critical path
            const float u0 = fmaf(xt, Bx[0], A[0]);
            const float u1 = fmaf(xt, Bx[1], A[1]);
            const float u2 = fmaf(xt, Bx[2], A[2]);

            // publish own r's, then read all 12 as three aligned quads
            asm volatile("st.shared.f32 [%0], %1;" :: "r"(stA), "f"(r0));
            asm volatile("st.shared.f32 [%0], %1;" :: "r"(stB), "f"(r1));
            asm volatile("st.shared.f32 [%0], %1;" :: "r"(stC), "f"(r2));
            __syncwarp();
            uint32_t q0, q1, q2, q3, q4, q5, q6, q7, q8, q9, qa, qb;
            asm volatile("ld.shared.v4.b32 {%0,%1,%2,%3}, [%4];"
                         : "=r"(q0), "=r"(q1), "=r"(q2), "=r"(q3) : "r"(exb));
            asm volatile("ld.shared.v4.b32 {%0,%1,%2,%3}, [%4];"
                         : "=r"(q4), "=r"(q5), "=r"(q6), "=r"(q7) : "r"(exb + 16u));
            asm volatile("ld.shared.v4.b32 {%0,%1,%2,%3}, [%4];"
                         : "=r"(q8), "=r"(q9), "=r"(qa), "=r"(qb) : "r"(exb + 32u));
            const uint64_t p0 = pack2u(q0, q1), p1 = pack2u(q2, q3);
            const uint64_t p2 = pack2u(q4, q5), p3 = pack2u(q6, q7);
            const uint64_t p4 = pack2u(q8, q9), p5 = pack2u(qa, qb);

            float rn[3];
            const float uu[3] = {u0, u1, u2};
#pragma unroll
            for (int i = 0; i < 3; i++) {
                uint64_t aA = fma2(Wp[i][0], p0, pack2(uu[i], 0.0f));
                uint64_t aB = mul2(Wp[i][1], p1);
                aA = fma2(Wp[i][2], p2, aA);
                aB = fma2(Wp[i][3], p3, aB);
                aA = fma2(Wp[i][4], p4, aA);
                aB = fma2(Wp[i][5], p5, aB);
                float lo, hi;
                unpack2(add2(aA, aB), lo, hi);
                const float s = lo + hi;
                rn[i] = rcpf(ex2f(s) + 1.0f);
            }
            r0 = rn[0]; r1 = rn[1]; r2 = rn[2];
        }
        __syncthreads();
    }

    // --- head on final hidden state: h[m] = 1 - 2 r[m] ---
    float g[12];
#pragma unroll
    for (int m = 0; m < 4; m++) {
        g[m + 0] = __shfl_sync(0xffffffffu, r0, m, 4);
        g[m + 4] = __shfl_sync(0xffffffffu, r1, m, 4);
        g[m + 8] = __shfl_sync(0xffffffffu, r2, m, 4);
    }
    if (k == 0) {
        float o0 = b_head[0];
        float o1 = b_head[1];
#pragma unroll
        for (int m = 0; m < 12; m++) {
            float h = fmaf(-2.0f, g[m], 1.0f);
            o0 = fmaf(W_head[m],      h, o0);
            o1 = fmaf(W_head[12 + m], h, o1);
        }
        out[batch * 2 + 0] = o0;
        out[batch * 2 + 1] = o1;
    }
}

extern "C" void kernel_launch(void* const* d_in, const int* in_sizes, int n_in,
                              void* d_out, int out_size)
{
    const float* x      = (const float*)d_in[0];
    const float* W_ih   = (const float*)d_in[1];
    const float* W_hh   = (const float*)d_in[2];
    const float* b_ih   = (const float*)d_in[3];
    const float* b_hh   = (const float*)d_in[4];
    const float* W_head = (const float*)d_in[5];
    const float* b_head = (const float*)d_in[6];
    float* out = (float*)d_out;

    tinyrnn_kernel<<<128, 128>>>(x, W_ih, W_hh, b_ih, b_hh, W_head, b_head, out);
}